// round 2
// baseline (speedup 1.0000x reference)
#include <cuda_runtime.h>
#include <cstdint>
#include <math.h>

#define NTOK 12544
#define CDIM 768
#define HDIM 3072
#define NEXP 8
#define TOPK 2
#define RDIM 16

#define BM 128
#define BN 128
#define BK 32
#define LDA 36   /* BK+4 : fragment banks (t*4+c) unique */
#define LDB 136  /* BN+8 : fragment banks (c*8+t) unique */

#define MOE_TT 64
#define WLD 770  /* MoE weight smem row stride: 770 % 32 == 2 -> conflict-free */

// ---------------- scratch (no allocations allowed) ----------------
__device__ float g_Xr[NTOK * CDIM];          // tf32-rounded x
__device__ float g_W1r[CDIM * HDIM];         // tf32-rounded w1
__device__ float g_W2r[HDIM * CDIM];         // tf32-rounded w2
__device__ float g_H[(size_t)NTOK * HDIM];   // gelu(x@w1+b1), tf32-rounded

// ---------------- helpers ----------------
__device__ __forceinline__ float gelu_f(float v) {
    return 0.5f * v * (1.0f + erff(v * 0.7071067811865476f));
}

__device__ __forceinline__ float to_tf32(float v) {
    uint32_t u;
    asm("cvt.rna.tf32.f32 %0, %1;" : "=r"(u) : "f"(v));
    return __uint_as_float(u);
}

__device__ __forceinline__ void cp_async16(void* smem, const void* gmem) {
    uint32_t s = (uint32_t)__cvta_generic_to_shared(smem);
    asm volatile("cp.async.cg.shared.global [%0], [%1], 16;\n" :: "r"(s), "l"(gmem));
}

__device__ __forceinline__ void mma_tf32(float (&d)[4], const uint32_t (&a)[4],
                                         const uint32_t (&b)[2]) {
    asm volatile(
        "mma.sync.aligned.m16n8k8.row.col.f32.tf32.tf32.f32 "
        "{%0,%1,%2,%3}, {%4,%5,%6,%7}, {%8,%9}, {%0,%1,%2,%3};\n"
        : "+f"(d[0]), "+f"(d[1]), "+f"(d[2]), "+f"(d[3])
        : "r"(a[0]), "r"(a[1]), "r"(a[2]), "r"(a[3]), "r"(b[0]), "r"(b[1]));
}

// ---------------- tf32 pre-rounding ----------------
__global__ void cvt_tf32_kernel(const float4* __restrict__ in,
                                float4* __restrict__ out, int n4) {
    int i = blockIdx.x * blockDim.x + threadIdx.x;
    if (i < n4) {
        float4 v = in[i];
        v.x = to_tf32(v.x);
        v.y = to_tf32(v.y);
        v.z = to_tf32(v.z);
        v.w = to_tf32(v.w);
        out[i] = v;
    }
}

// ---------------- tf32 tensor-core GEMM: C = op(A@B + bias) ----------------
// A [M,K] row-major (already tf32-rounded), B [K,N] row-major (tf32-rounded).
// fuseGelu: apply exact GELU and re-round output to tf32 (feeds GEMM2).
__global__ __launch_bounds__(256, 2)
void gemm_tf32_kernel(const float* __restrict__ A, const float* __restrict__ B,
                      const float* __restrict__ bias, float* __restrict__ C,
                      int M, int N, int K, int fuseGelu)
{
    extern __shared__ float sm[];
    float* As = sm;                    // [2][BM][LDA]
    float* Bs = sm + 2 * BM * LDA;     // [2][BK][LDB]

    const int tid  = threadIdx.x;
    const int lane = tid & 31;
    const int warp = tid >> 5;
    const int warpM = (warp >> 2) * 64;  // 2 warp-rows of 64
    const int warpN = (warp & 3) * 32;   // 4 warp-cols of 32
    const int t  = lane >> 2;            // groupID
    const int c4 = lane & 3;             // threadID_in_group

    const int m0 = blockIdx.y * BM;
    const int n0 = blockIdx.x * BN;

    const float* Ablk = A + (size_t)m0 * K;
    const float* Bblk = B + n0;

    // cp.async staging coordinates
    const int arow = tid >> 1;
    const int acol = (tid & 1) * 16;
    const int brow = tid >> 3;
    const int bcol = (tid & 7) * 16;

    auto issue = [&](int kt, int buf) {
        float* asn = As + buf * (BM * LDA);
        float* bsn = Bs + buf * (BK * LDB);
        const float* ag = Ablk + (size_t)arow * K + kt * BK + acol;
        #pragma unroll
        for (int i = 0; i < 4; i++)
            cp_async16(asn + arow * LDA + acol + i * 4, ag + i * 4);
        const float* bg = Bblk + (size_t)(kt * BK + brow) * N + bcol;
        #pragma unroll
        for (int i = 0; i < 4; i++)
            cp_async16(bsn + brow * LDB + bcol + i * 4, bg + i * 4);
        asm volatile("cp.async.commit_group;\n");
    };

    float acc[4][4][4];
    #pragma unroll
    for (int i = 0; i < 4; i++)
        #pragma unroll
        for (int j = 0; j < 4; j++)
            #pragma unroll
            for (int q = 0; q < 4; q++) acc[i][j][q] = 0.0f;

    const int kTiles = K / BK;
    issue(0, 0);

    for (int kt = 0; kt < kTiles; kt++) {
        asm volatile("cp.async.wait_group 0;\n");
        __syncthreads();                       // tile kt visible; prev buffer free
        if (kt + 1 < kTiles) issue(kt + 1, (kt + 1) & 1);

        const float* as = As + (kt & 1) * (BM * LDA);
        const float* bs = Bs + (kt & 1) * (BK * LDB);

        #pragma unroll
        for (int kk = 0; kk < BK; kk += 8) {
            uint32_t af[4][4], bf[4][2];
            #pragma unroll
            for (int i = 0; i < 4; i++) {
                const float* p = as + (warpM + i * 16 + t) * LDA + kk + c4;
                af[i][0] = __float_as_uint(p[0]);
                af[i][1] = __float_as_uint(p[8 * LDA]);
                af[i][2] = __float_as_uint(p[4]);
                af[i][3] = __float_as_uint(p[8 * LDA + 4]);
            }
            #pragma unroll
            for (int j = 0; j < 4; j++) {
                const float* q = bs + (kk + c4) * LDB + warpN + j * 8 + t;
                bf[j][0] = __float_as_uint(q[0]);
                bf[j][1] = __float_as_uint(q[4 * LDB]);
            }
            #pragma unroll
            for (int i = 0; i < 4; i++)
                #pragma unroll
                for (int j = 0; j < 4; j++)
                    mma_tf32(acc[i][j], af[i], bf[j]);
        }
    }

    // epilogue
    #pragma unroll
    for (int j = 0; j < 4; j++) {
        int col = n0 + warpN + j * 8 + c4 * 2;
        float bb0 = bias[col], bb1 = bias[col + 1];
        #pragma unroll
        for (int i = 0; i < 4; i++) {
            int row = m0 + warpM + i * 16 + t;
            float v00 = acc[i][j][0] + bb0;
            float v01 = acc[i][j][1] + bb1;
            float v10 = acc[i][j][2] + bb0;
            float v11 = acc[i][j][3] + bb1;
            if (fuseGelu) {
                v00 = to_tf32(gelu_f(v00));
                v01 = to_tf32(gelu_f(v01));
                v10 = to_tf32(gelu_f(v10));
                v11 = to_tf32(gelu_f(v11));
            }
            *(float2*)(C + (size_t)row * N + col)       = make_float2(v00, v01);
            *(float2*)(C + (size_t)(row + 8) * N + col) = make_float2(v10, v11);
        }
    }
}

// ---------------- top-k sparse MoE LoRA, atomically added to out ----------------
// Per 64-token tile: for each expert, cache its w_down^T / w_up in SMEM, build the
// (token, prob) list, then warp-per-assignment: down=gelu(x·Wd), out += p*down·Wu.
__global__ __launch_bounds__(256)
void moe_kernel(const float* __restrict__ x, const float* __restrict__ probs,
                const int* __restrict__ tidx, const float* __restrict__ w_down,
                const float* __restrict__ w_up, float* __restrict__ out)
{
    extern __shared__ float sm[];
    float* wdn = sm;                        // [RDIM][WLD] (transposed w_down[e])
    float* wup = sm + RDIM * WLD;           // [RDIM][WLD]
    float* pw_s = sm + 2 * RDIM * WLD;      // [128]
    int*   tok_s = (int*)(pw_s + 128);      // [128]
    int*   cnt   = tok_s + 128;

    const int tid  = threadIdx.x;
    const int lane = tid & 31;
    const int warp = tid >> 5;
    const int t0 = blockIdx.x * MOE_TT;

    for (int e = 0; e < NEXP; e++) {
        __syncthreads();  // previous expert fully done before smem reuse

        const float* wd = w_down + e * CDIM * RDIM;   // [C][R]
        for (int i2 = tid; i2 < CDIM * RDIM; i2 += 256) {
            int r = i2 & 15, c = i2 >> 4;
            wdn[r * WLD + c] = wd[i2];
        }
        const float* wu = w_up + e * RDIM * CDIM;     // [R][C]
        #pragma unroll
        for (int r = 0; r < RDIM; r++)
            for (int c = tid; c < CDIM; c += 256)
                wup[r * WLD + c] = wu[r * CDIM + c];

        if (tid == 0) *cnt = 0;
        __syncthreads();

        if (tid < MOE_TT * TOPK) {
            int tok = t0 + (tid >> 1);
            int k = tid & 1;
            if (tidx[tok * TOPK + k] == e) {
                int pos = atomicAdd(cnt, 1);
                tok_s[pos] = tok;
                pw_s[pos] = probs[tok * TOPK + k];
            }
        }
        __syncthreads();
        int nE = *cnt;

        for (int ent = warp; ent < nE; ent += 8) {
            int tok = tok_s[ent];
            const float* xr = x + (size_t)tok * CDIM;
            float xv[24];
            #pragma unroll
            for (int i = 0; i < 24; i++) xv[i] = xr[lane + 32 * i];

            float myd = 0.0f;
            #pragma unroll
            for (int r = 0; r < RDIM; r++) {
                float a = 0.0f;
                #pragma unroll
                for (int i = 0; i < 24; i++)
                    a += xv[i] * wdn[r * WLD + lane + 32 * i];
                #pragma unroll
                for (int o = 16; o > 0; o >>= 1)
                    a += __shfl_xor_sync(0xffffffffu, a, o);
                if (lane == r) myd = a;   // lane r keeps sum_r
            }
            if (lane < RDIM) myd = gelu_f(myd);

            float p = pw_s[ent];          // SCALING == 1.0
            float mc[24];
            #pragma unroll
            for (int i = 0; i < 24; i++) mc[i] = 0.0f;
            #pragma unroll
            for (int r = 0; r < RDIM; r++) {
                float dv = __shfl_sync(0xffffffffu, myd, r);
                #pragma unroll
                for (int i = 0; i < 24; i++)
                    mc[i] += dv * wup[r * WLD + lane + 32 * i];
            }
            float* orow = out + (size_t)tok * CDIM;
            #pragma unroll
            for (int i = 0; i < 24; i++)
                atomicAdd(orow + lane + 32 * i, p * mc[i]);
        }
    }
}

// ---------------- launch ----------------
extern "C" void kernel_launch(void* const* d_in, const int* in_sizes, int n_in,
                              void* d_out, int out_size) {
    const float* x     = (const float*)d_in[0];
    const float* probs = (const float*)d_in[1];
    const int*   tidx  = (const int*)d_in[2];
    const float* w1    = (const float*)d_in[3];
    const float* b1    = (const float*)d_in[4];
    const float* w2    = (const float*)d_in[5];
    const float* b2    = (const float*)d_in[6];
    const float* wdn   = (const float*)d_in[7];
    const float* wup   = (const float*)d_in[8];
    float* out = (float*)d_out;

    float *pXr, *pW1, *pW2, *pH;
    cudaGetSymbolAddress((void**)&pXr, g_Xr);
    cudaGetSymbolAddress((void**)&pW1, g_W1r);
    cudaGetSymbolAddress((void**)&pW2, g_W2r);
    cudaGetSymbolAddress((void**)&pH,  g_H);

    const int GEMM_SMEM = (2 * BM * LDA + 2 * BK * LDB) * 4;           // 70 KB
    const int MOE_SMEM  = (2 * RDIM * WLD + 128) * 4 + 128 * 4 + 16;   // ~99 KB
    cudaFuncSetAttribute(gemm_tf32_kernel,
                         cudaFuncAttributeMaxDynamicSharedMemorySize, GEMM_SMEM);
    cudaFuncSetAttribute(moe_kernel,
                         cudaFuncAttributeMaxDynamicSharedMemorySize, MOE_SMEM);

    // tf32 pre-rounding (unbiased rna rounding; truncation would bias ~2^-10)
    cvt_tf32_kernel<<<(NTOK * CDIM / 4 + 255) / 256, 256>>>(
        (const float4*)x, (float4*)pXr, NTOK * CDIM / 4);
    cvt_tf32_kernel<<<(CDIM * HDIM / 4 + 255) / 256, 256>>>(
        (const float4*)w1, (float4*)pW1, CDIM * HDIM / 4);
    cvt_tf32_kernel<<<(HDIM * CDIM / 4 + 255) / 256, 256>>>(
        (const float4*)w2, (float4*)pW2, HDIM * CDIM / 4);

    // H = tf32(gelu(x@w1 + b1))
    gemm_tf32_kernel<<<dim3(HDIM / BN, NTOK / BM), 256, GEMM_SMEM>>>(
        pXr, pW1, b1, pH, NTOK, HDIM, CDIM, 1);
    // out = H@w2 + b2
    gemm_tf32_kernel<<<dim3(CDIM / BN, NTOK / BM), 256, GEMM_SMEM>>>(
        pH, pW2, b2, out, NTOK, CDIM, HDIM, 0);
    // out += top-k sparse MoE LoRA
    moe_kernel<<<NTOK / MOE_TT, 256, MOE_SMEM>>>(x, probs, tidx, wdn, wup, out);
}

// round 5
// speedup vs baseline: 2.3067x; 2.3067x over previous
#include <cuda_runtime.h>
#include <cuda_fp16.h>
#include <cstdint>
#include <math.h>

#define NTOK 12544
#define CDIM 768
#define HDIM 3072
#define NEXP 8
#define TOPK 2
#define RDIM 16

// ---- fp16 mma.sync GEMM config ----
#define BM 128
#define BN 128
#define BK 64                    // 64 fp16 = 128 B per smem row
#define STAGES 3
#define ATILE (BM * 128)         // 16 KB per operand tile (BM rows x 128 B)
#define GEMM_SMEM (2 * STAGES * ATILE)   // 96 KB

#define MOE_TT 64
#define WLD 770

// ---------------- scratch (no allocations allowed) ----------------
__device__ __half g_Xh[NTOK * CDIM];            // fp16 x              [NTOK][CDIM]
__device__ __half g_W1t[(size_t)HDIM * CDIM];   // fp16 w1^T (K-major) [HDIM][CDIM]
__device__ __half g_W2t[(size_t)CDIM * HDIM];   // fp16 w2^T (K-major) [CDIM][HDIM]
__device__ __half g_H[(size_t)NTOK * HDIM];     // fp16 gelu(x@w1+b1)  [NTOK][HDIM]

// ---------------- helpers ----------------
__device__ __forceinline__ float gelu_f(float v) {
    return 0.5f * v * (1.0f + erff(v * 0.7071067811865476f));
}
__device__ __forceinline__ void cp_async16(uint32_t saddr, const void* gmem) {
    asm volatile("cp.async.cg.shared.global [%0], [%1], 16;\n" :: "r"(saddr), "l"(gmem));
}
__device__ __forceinline__ void ldmatrix_x4(uint32_t& r0, uint32_t& r1,
                                            uint32_t& r2, uint32_t& r3, uint32_t addr) {
    asm volatile("ldmatrix.sync.aligned.m8n8.x4.shared.b16 {%0,%1,%2,%3}, [%4];"
                 : "=r"(r0), "=r"(r1), "=r"(r2), "=r"(r3) : "r"(addr));
}
__device__ __forceinline__ void mma_fp16(float (&d)[4], const uint32_t (&a)[4],
                                         uint32_t b0, uint32_t b1) {
    asm volatile(
        "mma.sync.aligned.m16n8k16.row.col.f32.f16.f16.f32 "
        "{%0,%1,%2,%3}, {%4,%5,%6,%7}, {%8,%9}, {%0,%1,%2,%3};\n"
        : "+f"(d[0]), "+f"(d[1]), "+f"(d[2]), "+f"(d[3])
        : "r"(a[0]), "r"(a[1]), "r"(a[2]), "r"(a[3]), "r"(b0), "r"(b1));
}

// ---------------- x -> fp16 ----------------
__global__ void cvt_fp16_kernel(const float4* __restrict__ in,
                                __half2* __restrict__ out, int n4) {
    int i = blockIdx.x * blockDim.x + threadIdx.x;
    if (i < n4) {
        float4 v = in[i];
        out[2 * i]     = __floats2half2_rn(v.x, v.y);
        out[2 * i + 1] = __floats2half2_rn(v.z, v.w);
    }
}

// ---------------- transpose + fp16 round (weights -> K-major) ----------------
__global__ void transpose_fp16_kernel(const float* __restrict__ in,
                                      __half* __restrict__ out, int R, int Ccol) {
    __shared__ float t[32][33];
    int bx = blockIdx.x * 32;
    int by = blockIdx.y * 32;
    int tx = threadIdx.x, ty = threadIdx.y;
    #pragma unroll
    for (int i = 0; i < 32; i += 8)
        t[ty + i][tx] = in[(size_t)(by + ty + i) * Ccol + bx + tx];
    __syncthreads();
    #pragma unroll
    for (int i = 0; i < 32; i += 8)
        out[(size_t)(bx + ty + i) * R + by + tx] = __float2half_rn(t[tx][ty + i]);
}

// ---------------- fp16 mma.sync GEMM: out = op(A[M,K] @ Bt[N,K]^T + bias) ----------------
// A, Bt fp16 K-contiguous. outGelu=1 -> write fp16 gelu() to Ch; else write fp32 (+bias) to Cf.
__global__ __launch_bounds__(256, 2)
void gemm_fp16_kernel(const __half* __restrict__ A, const __half* __restrict__ Bt,
                      const float* __restrict__ bias, float* __restrict__ Cf,
                      __half* __restrict__ Ch, int M, int N, int K, int outGelu)
{
    extern __shared__ char smem[];
    const uint32_t sbase = (uint32_t)__cvta_generic_to_shared(smem);

    const int tid  = threadIdx.x;
    const int lane = tid & 31;
    const int wid  = tid >> 5;
    const int warpM = (wid >> 2) * 64;   // 2 warp-rows
    const int warpN = (wid & 3) * 32;    // 4 warp-cols
    const int m0 = blockIdx.y * BM;
    const int n0 = blockIdx.x * BN;
    const int kTiles = K / BK;

    // ldmatrix per-lane geometry
    const int q  = lane >> 3;        // 8x8 tile index within x4
    const int lr = lane & 7;         // row within tile
    // A: tiles (m0-7,k0-7),(m8-15,k0-7),(m0-7,k8-15),(m8-15,k8-15)
    const int a_qh = q >> 1;                       // k-half
    uint32_t a_off[4]; int a_r7[4];
    #pragma unroll
    for (int i = 0; i < 4; i++) {
        int row = warpM + i * 16 + (q & 1) * 8 + lr;
        a_r7[i] = row & 7;
        a_off[i] = (uint32_t)row * 128;
    }
    // B: tiles (n0-7,k0-7),(n0-7,k8-15),(n8-15,k0-7),(n8-15,k8-15)
    const int b_qh = q & 1;
    uint32_t b_off[2]; int b_r7[2];
    #pragma unroll
    for (int j2 = 0; j2 < 2; j2++) {
        int row = warpN + j2 * 16 + (q >> 1) * 8 + lr;
        b_r7[j2] = row & 7;
        b_off[j2] = (uint32_t)row * 128;
    }

    // staged tile loader (8 cp.async x 16B per thread per operand pair)
    auto load_tile = [&](int kt, int s) {
        const __half* Ag = A + (size_t)m0 * K + (size_t)kt * BK;
        const __half* Bg = Bt + (size_t)n0 * K + (size_t)kt * BK;
        uint32_t sa = sbase + s * ATILE;
        uint32_t sb = sbase + STAGES * ATILE + s * ATILE;
        #pragma unroll
        for (int i = 0; i < 4; i++) {
            int idx = i * 256 + tid;
            int row = idx >> 3;
            int c = idx & 7;
            uint32_t sw = (uint32_t)((c ^ (row & 7)) << 4);
            cp_async16(sa + row * 128 + sw, Ag + (size_t)row * K + c * 8);
            cp_async16(sb + row * 128 + sw, Bg + (size_t)row * K + c * 8);
        }
        asm volatile("cp.async.commit_group;\n");
    };

    float acc[4][4][4];
    #pragma unroll
    for (int i = 0; i < 4; i++)
        #pragma unroll
        for (int j = 0; j < 4; j++)
            #pragma unroll
            for (int e = 0; e < 4; e++) acc[i][j][e] = 0.0f;

    load_tile(0, 0);
    load_tile(1, 1);

    int stage = 0;
    for (int kt = 0; kt < kTiles; kt++) {
        asm volatile("cp.async.wait_group %0;\n" :: "n"(STAGES - 2));  // tile kt resident
        __syncthreads();  // all warps past tile kt-1 compute -> stage (kt+2)%3 reusable

        if (kt + STAGES - 1 < kTiles) {
            int s2 = stage + 2; if (s2 >= STAGES) s2 -= STAGES;
            load_tile(kt + STAGES - 1, s2);
        } else {
            asm volatile("cp.async.commit_group;\n");  // keep group count uniform
        }

        const uint32_t saA = sbase + stage * ATILE;
        const uint32_t saB = sbase + STAGES * ATILE + stage * ATILE;

        #pragma unroll
        for (int kk = 0; kk < 4; kk++) {             // 4 x (K=16)
            uint32_t a[4][4];
            #pragma unroll
            for (int i = 0; i < 4; i++)
                ldmatrix_x4(a[i][0], a[i][1], a[i][2], a[i][3],
                            saA + a_off[i] + (uint32_t)(((kk * 2 + a_qh) ^ a_r7[i]) << 4));
            uint32_t b[4][2];
            #pragma unroll
            for (int j2 = 0; j2 < 2; j2++) {
                uint32_t r0, r1, r2, r3;
                ldmatrix_x4(r0, r1, r2, r3,
                            saB + b_off[j2] + (uint32_t)(((kk * 2 + b_qh) ^ b_r7[j2]) << 4));
                b[j2 * 2][0] = r0; b[j2 * 2][1] = r1;
                b[j2 * 2 + 1][0] = r2; b[j2 * 2 + 1][1] = r3;
            }
            #pragma unroll
            for (int i = 0; i < 4; i++)
                #pragma unroll
                for (int j = 0; j < 4; j++)
                    mma_fp16(acc[i][j], a[i], b[j][0], b[j][1]);
        }
        if (++stage >= STAGES) stage -= STAGES;
    }

    // epilogue: thread (t,c4): d0,d1 = (row t, cols 2c4,2c4+1); d2,d3 = row t+8
    const int t  = lane >> 2;
    const int c4 = lane & 3;
    #pragma unroll
    for (int j = 0; j < 4; j++) {
        int col = n0 + warpN + j * 8 + 2 * c4;
        float bb0 = bias[col], bb1 = bias[col + 1];
        #pragma unroll
        for (int i = 0; i < 4; i++) {
            int row = m0 + warpM + i * 16 + t;
            float v00 = acc[i][j][0] + bb0;
            float v01 = acc[i][j][1] + bb1;
            float v10 = acc[i][j][2] + bb0;
            float v11 = acc[i][j][3] + bb1;
            if (outGelu) {
                *(__half2*)(Ch + (size_t)row * N + col) =
                    __floats2half2_rn(gelu_f(v00), gelu_f(v01));
                *(__half2*)(Ch + (size_t)(row + 8) * N + col) =
                    __floats2half2_rn(gelu_f(v10), gelu_f(v11));
            } else {
                *(float2*)(Cf + (size_t)row * N + col)       = make_float2(v00, v01);
                *(float2*)(Cf + (size_t)(row + 8) * N + col) = make_float2(v10, v11);
            }
        }
    }
}

// ---------------- top-k sparse MoE LoRA (unchanged) ----------------
__global__ __launch_bounds__(256)
void moe_kernel(const float* __restrict__ x, const float* __restrict__ probs,
                const int* __restrict__ tidx, const float* __restrict__ w_down,
                const float* __restrict__ w_up, float* __restrict__ out)
{
    extern __shared__ float sm[];
    float* wdn = sm;
    float* wup = sm + RDIM * WLD;
    float* pw_s = sm + 2 * RDIM * WLD;
    int*   tok_s = (int*)(pw_s + 128);
    int*   cnt   = tok_s + 128;

    const int tid  = threadIdx.x;
    const int lane = tid & 31;
    const int warp = tid >> 5;
    const int t0 = blockIdx.x * MOE_TT;

    for (int e = 0; e < NEXP; e++) {
        __syncthreads();

        const float* wd = w_down + e * CDIM * RDIM;
        for (int i2 = tid; i2 < CDIM * RDIM; i2 += 256) {
            int r = i2 & 15, c = i2 >> 4;
            wdn[r * WLD + c] = wd[i2];
        }
        const float* wu = w_up + e * RDIM * CDIM;
        #pragma unroll
        for (int r = 0; r < RDIM; r++)
            for (int c = tid; c < CDIM; c += 256)
                wup[r * WLD + c] = wu[r * CDIM + c];

        if (tid == 0) *cnt = 0;
        __syncthreads();

        if (tid < MOE_TT * TOPK) {
            int tok = t0 + (tid >> 1);
            int k = tid & 1;
            if (tidx[tok * TOPK + k] == e) {
                int pos = atomicAdd(cnt, 1);
                tok_s[pos] = tok;
                pw_s[pos] = probs[tok * TOPK + k];
            }
        }
        __syncthreads();
        int nE = *cnt;

        for (int ent = warp; ent < nE; ent += 8) {
            int tok = tok_s[ent];
            const float* xr = x + (size_t)tok * CDIM;
            float xv[24];
            #pragma unroll
            for (int i = 0; i < 24; i++) xv[i] = xr[lane + 32 * i];

            float myd = 0.0f;
            #pragma unroll
            for (int r = 0; r < RDIM; r++) {
                float a = 0.0f;
                #pragma unroll
                for (int i = 0; i < 24; i++)
                    a += xv[i] * wdn[r * WLD + lane + 32 * i];
                #pragma unroll
                for (int o = 16; o > 0; o >>= 1)
                    a += __shfl_xor_sync(0xffffffffu, a, o);
                if (lane == r) myd = a;
            }
            if (lane < RDIM) myd = gelu_f(myd);

            float p = pw_s[ent];
            float mc[24];
            #pragma unroll
            for (int i = 0; i < 24; i++) mc[i] = 0.0f;
            #pragma unroll
            for (int r = 0; r < RDIM; r++) {
                float dv = __shfl_sync(0xffffffffu, myd, r);
                #pragma unroll
                for (int i = 0; i < 24; i++)
                    mc[i] += dv * wup[r * WLD + lane + 32 * i];
            }
            float* orow = out + (size_t)tok * CDIM;
            #pragma unroll
            for (int i = 0; i < 24; i++)
                atomicAdd(orow + lane + 32 * i, p * mc[i]);
        }
    }
}

// ---------------- launch ----------------
extern "C" void kernel_launch(void* const* d_in, const int* in_sizes, int n_in,
                              void* d_out, int out_size) {
    const float* x     = (const float*)d_in[0];
    const float* probs = (const float*)d_in[1];
    const int*   tidx  = (const int*)d_in[2];
    const float* w1    = (const float*)d_in[3];
    const float* b1    = (const float*)d_in[4];
    const float* w2    = (const float*)d_in[5];
    const float* b2    = (const float*)d_in[6];
    const float* wdn   = (const float*)d_in[7];
    const float* wup   = (const float*)d_in[8];
    float* out = (float*)d_out;

    __half *pXh, *pW1t, *pW2t, *pH;
    cudaGetSymbolAddress((void**)&pXh,  g_Xh);
    cudaGetSymbolAddress((void**)&pW1t, g_W1t);
    cudaGetSymbolAddress((void**)&pW2t, g_W2t);
    cudaGetSymbolAddress((void**)&pH,   g_H);

    const int MOE_SMEM = (2 * RDIM * WLD + 128) * 4 + 128 * 4 + 16;
    cudaFuncSetAttribute(gemm_fp16_kernel,
                         cudaFuncAttributeMaxDynamicSharedMemorySize, GEMM_SMEM);
    cudaFuncSetAttribute(moe_kernel,
                         cudaFuncAttributeMaxDynamicSharedMemorySize, MOE_SMEM);

    // x -> fp16
    cvt_fp16_kernel<<<(NTOK * CDIM / 4 + 255) / 256, 256>>>(
        (const float4*)x, (__half2*)pXh, NTOK * CDIM / 4);
    // w1 [C,H] -> W1t [H,C] fp16 ; w2 [H,C] -> W2t [C,H] fp16
    transpose_fp16_kernel<<<dim3(HDIM / 32, CDIM / 32), dim3(32, 8)>>>(w1, pW1t, CDIM, HDIM);
    transpose_fp16_kernel<<<dim3(CDIM / 32, HDIM / 32), dim3(32, 8)>>>(w2, pW2t, HDIM, CDIM);

    // H = fp16(gelu(x@w1 + b1))
    gemm_fp16_kernel<<<dim3(HDIM / BN, NTOK / BM), 256, GEMM_SMEM>>>(
        pXh, pW1t, b1, nullptr, pH, NTOK, HDIM, CDIM, 1);
    // out = H@w2 + b2
    gemm_fp16_kernel<<<dim3(CDIM / BN, NTOK / BM), 256, GEMM_SMEM>>>(
        pH, pW2t, b2, out, nullptr, NTOK, CDIM, HDIM, 0);
    // out += top-k sparse MoE LoRA
    moe_kernel<<<NTOK / MOE_TT, 256, MOE_SMEM>>>(x, probs, tidx, wdn, wup, out);
}

// round 11
// speedup vs baseline: 2.3231x; 1.0071x over previous
#include <cuda_runtime.h>
#include <cuda_fp16.h>
#include <cstdint>
#include <math.h>

#define NTOK 12544
#define CDIM 768
#define HDIM 3072
#define NEXP 8
#define TOPK 2
#define RDIM 16

// ---- fp16 mma.sync GEMM config: CTA 128x128, 4 warps of 64x64 ----
#define BM 128
#define BN 128
#define BK 64                    // 64 fp16 = 128 B per smem row
#define STAGES 3
#define ATILE (BM * 128)         // 16 KB per operand tile
#define GEMM_SMEM (2 * STAGES * ATILE)   // 96 KB

#define MOE_TT 64
#define WROW 776                 // MoE weight smem row stride (floats), 16B-aligned

// ---------------- scratch (no allocations allowed) ----------------
__device__ __half g_Xh[NTOK * CDIM];            // fp16 x              [NTOK][CDIM]
__device__ __half g_W1t[(size_t)HDIM * CDIM];   // fp16 w1^T (K-major) [HDIM][CDIM]
__device__ __half g_W2t[(size_t)CDIM * HDIM];   // fp16 w2^T (K-major) [CDIM][HDIM]
__device__ __half g_H[(size_t)NTOK * HDIM];     // fp16 gelu(x@w1+b1)  [NTOK][HDIM]

// ---------------- helpers ----------------
__device__ __forceinline__ float gelu_f(float v) {
    return 0.5f * v * (1.0f + erff(v * 0.7071067811865476f));
}
__device__ __forceinline__ void cp_async16(uint32_t saddr, const void* gmem) {
    asm volatile("cp.async.cg.shared.global [%0], [%1], 16;\n" :: "r"(saddr), "l"(gmem));
}
__device__ __forceinline__ void ldmatrix_x4(uint32_t& r0, uint32_t& r1,
                                            uint32_t& r2, uint32_t& r3, uint32_t addr) {
    asm volatile("ldmatrix.sync.aligned.m8n8.x4.shared.b16 {%0,%1,%2,%3}, [%4];"
                 : "=r"(r0), "=r"(r1), "=r"(r2), "=r"(r3) : "r"(addr));
}
__device__ __forceinline__ void mma_fp16(float (&d)[4], const uint32_t (&a)[4],
                                         uint32_t b0, uint32_t b1) {
    asm volatile(
        "mma.sync.aligned.m16n8k16.row.col.f32.f16.f16.f32 "
        "{%0,%1,%2,%3}, {%4,%5,%6,%7}, {%8,%9}, {%0,%1,%2,%3};\n"
        : "+f"(d[0]), "+f"(d[1]), "+f"(d[2]), "+f"(d[3])
        : "r"(a[0]), "r"(a[1]), "r"(a[2]), "r"(a[3]), "r"(b0), "r"(b1));
}

// ---------------- x -> fp16 ----------------
__global__ void cvt_fp16_kernel(const float4* __restrict__ in,
                                __half2* __restrict__ out, int n4) {
    int i = blockIdx.x * blockDim.x + threadIdx.x;
    if (i < n4) {
        float4 v = in[i];
        out[2 * i]     = __floats2half2_rn(v.x, v.y);
        out[2 * i + 1] = __floats2half2_rn(v.z, v.w);
    }
}

// ---------------- transpose + fp16 round (weights -> K-major) ----------------
__global__ void transpose_fp16_kernel(const float* __restrict__ in,
                                      __half* __restrict__ out, int R, int Ccol) {
    __shared__ float t[32][33];
    int bx = blockIdx.x * 32;
    int by = blockIdx.y * 32;
    int tx = threadIdx.x, ty = threadIdx.y;
    #pragma unroll
    for (int i = 0; i < 32; i += 8)
        t[ty + i][tx] = in[(size_t)(by + ty + i) * Ccol + bx + tx];
    __syncthreads();
    #pragma unroll
    for (int i = 0; i < 32; i += 8)
        out[(size_t)(bx + ty + i) * R + by + tx] = __float2half_rn(t[tx][ty + i]);
}

// ---------------- fp16 mma.sync GEMM: out = op(A[M,K] @ Bt[N,K]^T + bias) ----------------
// 128 threads, 4 warps of 64x64. outGelu=1 -> fp16 gelu() to Ch; else fp32 (+bias) to Cf.
__global__ __launch_bounds__(128, 2)
void gemm_fp16_kernel(const __half* __restrict__ A, const __half* __restrict__ Bt,
                      const float* __restrict__ bias, float* __restrict__ Cf,
                      __half* __restrict__ Ch, int M, int N, int K, int outGelu)
{
    extern __shared__ char smem[];
    const uint32_t sbase = (uint32_t)__cvta_generic_to_shared(smem);

    const int tid  = threadIdx.x;
    const int lane = tid & 31;
    const int wid  = tid >> 5;            // 0..3
    const int warpM = (wid >> 1) * 64;    // 2 warp rows
    const int warpN = (wid & 1) * 64;     // 2 warp cols
    const int m0 = blockIdx.y * BM;
    const int n0 = blockIdx.x * BN;
    const int kTiles = K / BK;

    // ldmatrix per-lane geometry
    const int q  = lane >> 3;        // x4 sub-tile index
    const int lr = lane & 7;
    // A tiles: (m0-7,k0-7),(m8-15,k0-7),(m0-7,k8-15),(m8-15,k8-15)
    const int a_qh = q >> 1;
    uint32_t a_off[4]; int a_r7[4];
    #pragma unroll
    for (int i = 0; i < 4; i++) {
        int row = warpM + i * 16 + (q & 1) * 8 + lr;
        a_r7[i] = row & 7;
        a_off[i] = (uint32_t)row * 128;
    }
    // B tiles: (n0-7,k0-7),(n0-7,k8-15),(n8-15,k0-7),(n8-15,k8-15)
    const int b_qh = q & 1;
    uint32_t b_off[4]; int b_r7[4];
    #pragma unroll
    for (int j2 = 0; j2 < 4; j2++) {
        int row = warpN + j2 * 16 + (q >> 1) * 8 + lr;
        b_r7[j2] = row & 7;
        b_off[j2] = (uint32_t)row * 128;
    }

    // staged tile loader: 128 threads x 8 chunks x 16B per operand
    auto load_tile = [&](int kt, int s) {
        const __half* Ag = A + (size_t)m0 * K + (size_t)kt * BK;
        const __half* Bg = Bt + (size_t)n0 * K + (size_t)kt * BK;
        uint32_t sa = sbase + s * ATILE;
        uint32_t sb = sbase + STAGES * ATILE + s * ATILE;
        #pragma unroll
        for (int i = 0; i < 8; i++) {
            int idx = i * 128 + tid;
            int row = idx >> 3;
            int c = idx & 7;
            uint32_t sw = (uint32_t)((c ^ (row & 7)) << 4);
            cp_async16(sa + row * 128 + sw, Ag + (size_t)row * K + c * 8);
            cp_async16(sb + row * 128 + sw, Bg + (size_t)row * K + c * 8);
        }
        asm volatile("cp.async.commit_group;\n");
    };

    float acc[4][8][4];
    #pragma unroll
    for (int i = 0; i < 4; i++)
        #pragma unroll
        for (int j = 0; j < 8; j++)
            #pragma unroll
            for (int e = 0; e < 4; e++) acc[i][j][e] = 0.0f;

    load_tile(0, 0);
    load_tile(1, 1);

    int stage = 0;
    for (int kt = 0; kt < kTiles; kt++) {
        asm volatile("cp.async.wait_group %0;\n" :: "n"(STAGES - 2));
        __syncthreads();

        if (kt + STAGES - 1 < kTiles) {
            int s2 = stage + 2; if (s2 >= STAGES) s2 -= STAGES;
            load_tile(kt + STAGES - 1, s2);
        } else {
            asm volatile("cp.async.commit_group;\n");
        }

        const uint32_t saA = sbase + stage * ATILE;
        const uint32_t saB = sbase + STAGES * ATILE + stage * ATILE;

        #pragma unroll
        for (int kk = 0; kk < 4; kk++) {             // 4 x (K=16)
            uint32_t a[4][4];
            #pragma unroll
            for (int i = 0; i < 4; i++)
                ldmatrix_x4(a[i][0], a[i][1], a[i][2], a[i][3],
                            saA + a_off[i] + (uint32_t)(((kk * 2 + a_qh) ^ a_r7[i]) << 4));
            uint32_t b[8][2];
            #pragma unroll
            for (int j2 = 0; j2 < 4; j2++) {
                uint32_t r0, r1, r2, r3;
                ldmatrix_x4(r0, r1, r2, r3,
                            saB + b_off[j2] + (uint32_t)(((kk * 2 + b_qh) ^ b_r7[j2]) << 4));
                b[j2 * 2][0] = r0; b[j2 * 2][1] = r1;
                b[j2 * 2 + 1][0] = r2; b[j2 * 2 + 1][1] = r3;
            }
            #pragma unroll
            for (int i = 0; i < 4; i++)
                #pragma unroll
                for (int j = 0; j < 8; j++)
                    mma_fp16(acc[i][j], a[i], b[j][0], b[j][1]);
        }
        if (++stage >= STAGES) stage -= STAGES;
    }

    // epilogue
    const int t  = lane >> 2;
    const int c4 = lane & 3;
    #pragma unroll
    for (int j = 0; j < 8; j++) {
        int col = n0 + warpN + j * 8 + 2 * c4;
        float bb0 = bias[col], bb1 = bias[col + 1];
        #pragma unroll
        for (int i = 0; i < 4; i++) {
            int row = m0 + warpM + i * 16 + t;
            float v00 = acc[i][j][0] + bb0;
            float v01 = acc[i][j][1] + bb1;
            float v10 = acc[i][j][2] + bb0;
            float v11 = acc[i][j][3] + bb1;
            if (outGelu) {
                *(__half2*)(Ch + (size_t)row * N + col) =
                    __floats2half2_rn(gelu_f(v00), gelu_f(v01));
                *(__half2*)(Ch + (size_t)(row + 8) * N + col) =
                    __floats2half2_rn(gelu_f(v10), gelu_f(v11));
            } else {
                *(float2*)(Cf + (size_t)row * N + col)       = make_float2(v00, v01);
                *(float2*)(Cf + (size_t)(row + 8) * N + col) = make_float2(v10, v11);
            }
        }
    }
}

// ---------------- top-k sparse MoE LoRA: atomic-free, float4 RMW ----------------
// Each block exclusively owns tokens [t0, t0+64). Experts are barrier-separated;
// per (expert, token) at most one entry (duplicate expert slots folded: p0+p1),
// so warps touch disjoint output rows -> plain ld/add/st is race-free.
__global__ __launch_bounds__(256)
void moe_kernel(const float* __restrict__ x, const float* __restrict__ probs,
                const int* __restrict__ tidx, const float* __restrict__ w_down,
                const float* __restrict__ w_up, float* __restrict__ out)
{
    extern __shared__ float sm[];
    float* wdn = sm;                    // [RDIM][WROW]  (w_down[e]^T)
    float* wup = sm + RDIM * WROW;      // [RDIM][WROW]
    float* pw_s = sm + 2 * RDIM * WROW; // [64]
    int*   tok_s = (int*)(pw_s + 64);   // [64]
    int*   cnt   = tok_s + 64;

    const int tid  = threadIdx.x;
    const int lane = tid & 31;
    const int warp = tid >> 5;
    const int t0 = blockIdx.x * MOE_TT;

    for (int e = 0; e < NEXP; e++) {
        __syncthreads();  // prior expert's smem use + out RMW complete

        const float* wd = w_down + e * CDIM * RDIM;   // [C][R]
        for (int i2 = tid; i2 < CDIM * RDIM; i2 += 256) {
            int r = i2 & 15, c = i2 >> 4;
            wdn[r * WROW + c] = wd[i2];
        }
        const float* wu = w_up + e * RDIM * CDIM;     // [R][C]
        #pragma unroll
        for (int r = 0; r < RDIM; r++)
            for (int c = tid; c < CDIM; c += 256)
                wup[r * WROW + c] = wu[r * CDIM + c];

        if (tid == 0) *cnt = 0;
        __syncthreads();

        if (tid < MOE_TT) {               // one thread per token: dedupe expert slots
            int tok = t0 + tid;
            int i0 = tidx[tok * TOPK];
            int i1 = tidx[tok * TOPK + 1];
            float p = 0.0f; bool has = false;
            if (i0 == e) { p = probs[tok * TOPK] + (i1 == e ? probs[tok * TOPK + 1] : 0.0f); has = true; }
            else if (i1 == e) { p = probs[tok * TOPK + 1]; has = true; }
            if (has) {
                int pos = atomicAdd(cnt, 1);
                tok_s[pos] = tok;
                pw_s[pos] = p;
            }
        }
        __syncthreads();
        int nE = *cnt;

        for (int ent = warp; ent < nE; ent += 8) {
            int tok = tok_s[ent];
            const float4* xr = (const float4*)(x + (size_t)tok * CDIM);
            float4 xv[6];
            #pragma unroll
            for (int i = 0; i < 6; i++) xv[i] = xr[lane + 32 * i];

            float myd = 0.0f;
            #pragma unroll
            for (int r = 0; r < RDIM; r++) {
                float a = 0.0f;
                #pragma unroll
                for (int i = 0; i < 6; i++) {
                    float4 w = *(const float4*)&wdn[r * WROW + 4 * (lane + 32 * i)];
                    a += xv[i].x * w.x + xv[i].y * w.y + xv[i].z * w.z + xv[i].w * w.w;
                }
                #pragma unroll
                for (int o = 16; o > 0; o >>= 1)
                    a += __shfl_xor_sync(0xffffffffu, a, o);
                if (lane == r) myd = a;
            }
            if (lane < RDIM) myd = gelu_f(myd);

            float p = pw_s[ent];
            float4 mc[6];
            #pragma unroll
            for (int i = 0; i < 6; i++) mc[i] = make_float4(0.f, 0.f, 0.f, 0.f);
            #pragma unroll
            for (int r = 0; r < RDIM; r++) {
                float dv = __shfl_sync(0xffffffffu, myd, r);
                #pragma unroll
                for (int i = 0; i < 6; i++) {
                    float4 w = *(const float4*)&wup[r * WROW + 4 * (lane + 32 * i)];
                    mc[i].x += dv * w.x; mc[i].y += dv * w.y;
                    mc[i].z += dv * w.z; mc[i].w += dv * w.w;
                }
            }
            float4* orow = (float4*)(out + (size_t)tok * CDIM);
            #pragma unroll
            for (int i = 0; i < 6; i++) {
                float4 o = orow[lane + 32 * i];
                o.x += p * mc[i].x; o.y += p * mc[i].y;
                o.z += p * mc[i].z; o.w += p * mc[i].w;
                orow[lane + 32 * i] = o;
            }
        }
    }
}

// ---------------- launch ----------------
extern "C" void kernel_launch(void* const* d_in, const int* in_sizes, int n_in,
                              void* d_out, int out_size) {
    const float* x     = (const float*)d_in[0];
    const float* probs = (const float*)d_in[1];
    const int*   tidx  = (const int*)d_in[2];
    const float* w1    = (const float*)d_in[3];
    const float* b1    = (const float*)d_in[4];
    const float* w2    = (const float*)d_in[5];
    const float* b2    = (const float*)d_in[6];
    const float* wdn   = (const float*)d_in[7];
    const float* wup   = (const float*)d_in[8];
    float* out = (float*)d_out;

    __half *pXh, *pW1t, *pW2t, *pH;
    cudaGetSymbolAddress((void**)&pXh,  g_Xh);
    cudaGetSymbolAddress((void**)&pW1t, g_W1t);
    cudaGetSymbolAddress((void**)&pW2t, g_W2t);
    cudaGetSymbolAddress((void**)&pH,   g_H);

    const int MOE_SMEM = (2 * RDIM * WROW + 64) * 4 + 64 * 4 + 16;
    cudaFuncSetAttribute(gemm_fp16_kernel,
                         cudaFuncAttributeMaxDynamicSharedMemorySize, GEMM_SMEM);
    cudaFuncSetAttribute(moe_kernel,
                         cudaFuncAttributeMaxDynamicSharedMemorySize, MOE_SMEM);

    // x -> fp16
    cvt_fp16_kernel<<<(NTOK * CDIM / 4 + 255) / 256, 256>>>(
        (const float4*)x, (__half2*)pXh, NTOK * CDIM / 4);
    // w1 [C,H] -> W1t [H,C] fp16 ; w2 [H,C] -> W2t [C,H] fp16
    transpose_fp16_kernel<<<dim3(HDIM / 32, CDIM / 32), dim3(32, 8)>>>(w1, pW1t, CDIM, HDIM);
    transpose_fp16_kernel<<<dim3(CDIM / 32, HDIM / 32), dim3(32, 8)>>>(w2, pW2t, HDIM, CDIM);

    // H = fp16(gelu(x@w1 + b1))
    gemm_fp16_kernel<<<dim3(HDIM / BN, NTOK / BM), 128, GEMM_SMEM>>>(
        pXh, pW1t, b1, nullptr, pH, NTOK, HDIM, CDIM, 1);
    // out = H@w2 + b2
    gemm_fp16_kernel<<<dim3(CDIM / BN, NTOK / BM), 128, GEMM_SMEM>>>(
        pH, pW2t, b2, out, nullptr, NTOK, CDIM, HDIM, 0);
    // out += top-k sparse MoE LoRA (atomic-free)
    moe_kernel<<<NTOK / MOE_TT, 256, MOE_SMEM>>>(x, probs, tidx, wdn, wup, out);
}